// round 7
// baseline (speedup 1.0000x reference)
#include <cuda_runtime.h>
#include <math.h>
#include <stdint.h>

// Problem constants
#define T_STEPS 512
#define NBATCH  1024
#define IDIM    64
#define RDIM    256
#define NCTA    256
#define NTHR    256
#define BM      64   // batch rows per CTA
#define BN      16   // output cols per CTA

typedef unsigned long long u64;

// -------- global scratch --------
// Activations in per-row-tile k-major pair-packed layout:
//   elem(tile bi, k, row r=2*pl+e) at base(bi) + k*64 + pl*2 + e
__device__ float g_h[NBATCH * RDIM];        // [16][256][32][2]
__device__ float g_cat[NBATCH * 2 * RDIM];  // [16][512][32][2]
__device__ float g_m[NBATCH * RDIM];        // [16][256][32][2]
__device__ float g_r1p[64 * NBATCH];        // regressor partials [bj*4+wc][1024]
__device__ unsigned g_bar_count = 0;
__device__ unsigned g_bar_gen = 0;

// -------- packed f32x2 helpers --------
__device__ __forceinline__ u64 dup2(float w) {
    u64 r; asm("mov.b64 %0, {%1, %1};" : "=l"(r) : "f"(w)); return r;
}
__device__ __forceinline__ void ffma2(u64& d, u64 a, u64 b) {
    asm("fma.rn.f32x2 %0, %1, %2, %0;" : "+l"(d) : "l"(a), "l"(b));
}
__device__ __forceinline__ float2 unpack2(u64 v) {
    float2 f; asm("mov.b64 {%0, %1}, %2;" : "=f"(f.x), "=f"(f.y) : "l"(v)); return f;
}

// -------- cp.async helpers (L1-bypass for cross-CTA coherence) --------
__device__ __forceinline__ void cp_async16(float* sdst, const float* gsrc) {
    unsigned s = (unsigned)__cvta_generic_to_shared(sdst);
    asm volatile("cp.async.cg.shared.global [%0], [%1], 16;" :: "r"(s), "l"(gsrc));
}
__device__ __forceinline__ void cp_commit() { asm volatile("cp.async.commit_group;"); }
template <int N>
__device__ __forceinline__ void cp_wait() {
    asm volatile("cp.async.wait_group %0;" :: "n"(N));
}

// -------- grid-wide sense-reversing barrier --------
__device__ __forceinline__ void grid_barrier() {
    __threadfence();
    __syncthreads();
    if (threadIdx.x == 0) {
        unsigned g = *((volatile unsigned*)&g_bar_gen);
        unsigned old = atomicAdd(&g_bar_count, 1u);
        if (old == NCTA - 1) {
            g_bar_count = 0;
            __threadfence();
            *((volatile unsigned*)&g_bar_gen) = g + 1;
        } else {
            unsigned cur;
            do {
                asm volatile("ld.acquire.gpu.global.u32 %0, [%1];"
                             : "=r"(cur) : "l"(&g_bar_gen));
            } while (cur == g);
        }
    }
    __syncthreads();
}

// -------- stage one contiguous 4KB chunk (16k x 64 floats), one group --------
__device__ __forceinline__ void stage1k(float* buf, const float* __restrict__ g) {
    cp_async16(buf + threadIdx.x * 4, g + threadIdx.x * 4);
    cp_commit();
}

// -------- compute one staged 16k chunk --------
// As: [16 k][64 floats]. Thread: pairs plbase, plbase+1 x 1 col.
// acc: a[0] = pair plbase (2 rows packed), a[1] = pair plbase+1.
template <bool FUSE2>
__device__ __forceinline__ void compute_chunk(
    const float* __restrict__ As,
    const float* __restrict__ w1, const float* __restrict__ w2,
    u64 a1[2], u64 a2[2], int aoff, int woff)
{
    #pragma unroll
    for (int k2 = 0; k2 < 8; k2++) {
        ulonglong2 A0 = *(const ulonglong2*)(As + k2 * 128 + aoff);       // k even
        ulonglong2 A1 = *(const ulonglong2*)(As + k2 * 128 + 64 + aoff);  // k odd
        float2 w = *(const float2*)(w1 + k2 * 32 + woff);
        u64 w0 = dup2(w.x), w1d = dup2(w.y);
        ffma2(a1[0], A0.x, w0);  ffma2(a1[1], A0.y, w0);
        ffma2(a1[0], A1.x, w1d); ffma2(a1[1], A1.y, w1d);
        if constexpr (FUSE2) {
            float2 v = *(const float2*)(w2 + k2 * 32 + woff);
            u64 v0 = dup2(v.x), v1 = dup2(v.y);
            ffma2(a2[0], A0.x, v0); ffma2(a2[1], A0.y, v0);
            ffma2(a2[0], A1.x, v1); ffma2(a2[1], A1.y, v1);
        }
    }
}

// -------- pipelined GEMM over NCH 16k chunks (4-buffer ring, 1 sync/chunk) ---
template <int NCH, bool FUSE2>
__device__ __forceinline__ void gemm_pipe(
    const float* __restrict__ gbase,
    const float* __restrict__ W1, const float* __restrict__ W2,
    float* bufs, u64 a1[2], u64 a2[2], int aoff, int woff)
{
    stage1k(bufs,        gbase);
    stage1k(bufs + 1024, gbase + 1024);
    stage1k(bufs + 2048, gbase + 2048);
    for (int i = 0; i < NCH; i++) {
        if (i + 2 < NCH)      { cp_wait<2>(); }
        else if (i + 1 < NCH) { cp_wait<1>(); }
        else                  { cp_wait<0>(); }
        __syncthreads();
        if (i + 3 < NCH) stage1k(bufs + ((i + 3) & 3) * 1024, gbase + (i + 3) * 1024);
        compute_chunk<FUSE2>(bufs + (i & 3) * 1024, W1 + i * 256, W2 + i * 256,
                             a1, a2, aoff, woff);
    }
}

__global__ void __launch_bounds__(NTHR, 2)
recurrent_kernel(const float* __restrict__ inputs,
                 const float* __restrict__ Whp, const float* __restrict__ bhp,
                 const float* __restrict__ Wcp, const float* __restrict__ bcp,
                 const float* __restrict__ Wm,  const float* __restrict__ bm,
                 const float* __restrict__ Whpost, const float* __restrict__ bhpost,
                 const float* __restrict__ Wr1, const float* __restrict__ br1,
                 const float* __restrict__ Wr2, const float* __restrict__ br2,
                 float* __restrict__ out)
{
    extern __shared__ float smem[];
    float* Whp_p    = smem;                 // 4096 (256k x 16c packed)
    float* Wr1_p    = Whp_p    + 4096;      // 4096
    float* Whpost_p = Wr1_p    + 4096;      // 4096
    float* Wm_p     = Whpost_p + 4096;      // 8192 (512k x 16c)
    float* Wcp_p    = Wm_p     + 8192;      // 1024 (64k x 16c)
    float* bias_s   = Wcp_p    + 1024;      // 128
    float* bufs     = bias_s   + 128;       // 4 x 1024

    const int tid  = threadIdx.x;
    const int wid  = tid >> 5;
    const int lane = tid & 31;
    const int wr = wid & 1;          // row half (32 rows)
    const int wc = wid >> 1;         // col group 0..3 (4 cols each)
    const int lr = lane >> 2;        // lane row 0..7
    const int lc = lane & 3;         // lane col 0..3
    const int plbase = wr * 16 + lr * 2;   // first local pair (of 2)
    const int cc     = wc * 4 + lc;        // local col 0..15
    const int aoff   = plbase * 2;
    const int woff   = cc * 2;

    const int bi   = blockIdx.x >> 4;   // row tile 0..15
    const int bj   = blockIdx.x & 15;   // col tile 0..15
    const int row0 = bi * BM;
    const int c0   = bj * BN;

    const int hbase   = bi * (RDIM * BM);       // 16384 floats per tile
    const int catbase = bi * (2 * RDIM * BM);   // 32768

    // ---- build packed weight slices: Wp[(k>>1)*32 + col*2 + (k&1)] ----
    for (int i = tid; i < 256 * BN; i += NTHR) {
        int k = i >> 4, col = i & 15;
        int d = (k >> 1) * 32 + col * 2 + (k & 1);
        Whp_p[d]    = Whp[k * RDIM + c0 + col];
        Wr1_p[d]    = Wr1[k * RDIM + c0 + col];
        Whpost_p[d] = Whpost[k * RDIM + c0 + col];
    }
    for (int i = tid; i < 512 * BN; i += NTHR) {
        int k = i >> 4, col = i & 15;
        Wm_p[(k >> 1) * 32 + col * 2 + (k & 1)] = Wm[k * RDIM + c0 + col];
    }
    for (int i = tid; i < 64 * BN; i += NTHR) {
        int k = i >> 4, col = i & 15;
        Wcp_p[(k >> 1) * 32 + col * 2 + (k & 1)] = Wcp[k * RDIM + c0 + col];
    }
    if (tid < 16) {
        bias_s[tid]      = bhp[c0 + tid];
        bias_s[16 + tid] = bcp[c0 + tid];
        bias_s[32 + tid] = bm[c0 + tid];
        bias_s[48 + tid] = bhpost[c0 + tid];
        bias_s[64 + tid] = br1[c0 + tid];
        bias_s[80 + tid] = Wr2[c0 + tid];
    }
    const float br2v = __ldg(br2);
    __syncthreads();

    for (int t = 0; t < T_STEPS; t++) {
        // ================= Phase A =================
        // ---- stage x_t (row-major, XOR-swizzled 16B slots) into all 4 bufs --
        {
            const float* xg = inputs + (size_t)t * NBATCH * IDIM + (size_t)row0 * IDIM;
            #pragma unroll
            for (int i2 = 0; i2 < 4; i2++) {
                int u = tid + i2 * NTHR;
                int r = u >> 4, s = u & 15;
                cp_async16(bufs + r * 64 + ((s ^ ((r >> 2) & 7)) << 2),
                           xg + r * 64 + s * 4);
            }
            cp_commit();
            cp_wait<0>();
            __syncthreads();
        }
        // ---- S0: tcp = tanh(x @ Wcp + bcp) -> cat[:, 256:512] ----
        {
            float aS[4];
            #pragma unroll
            for (int j = 0; j < 4; j++) aS[j] = bias_s[16 + cc];
            #pragma unroll 4
            for (int k4 = 0; k4 < 16; k4++) {
                float2 wA = *(const float2*)(Wcp_p + (2 * k4) * 32 + woff);
                float2 wB = *(const float2*)(Wcp_p + (2 * k4 + 1) * 32 + woff);
                #pragma unroll
                for (int j = 0; j < 4; j++) {
                    int r = wr * 32 + lr * 4 + j;
                    float4 a = *(const float4*)(bufs + r * 64 + ((k4 ^ ((r >> 2) & 7)) << 2));
                    aS[j] = fmaf(a.x, wA.x, aS[j]);
                    aS[j] = fmaf(a.y, wA.y, aS[j]);
                    aS[j] = fmaf(a.z, wB.x, aS[j]);
                    aS[j] = fmaf(a.w, wB.y, aS[j]);
                }
            }
            size_t xcol = catbase + (size_t)(RDIM + c0 + cc) * 64;
            *(float2*)(g_cat + xcol + plbase * 2)
                = make_float2(tanhf(aS[0]), tanhf(aS[1]));
            *(float2*)(g_cat + xcol + (plbase + 1) * 2)
                = make_float2(tanhf(aS[2]), tanhf(aS[3]));
            __syncthreads();   // bufs reused by the h pipeline below
        }

        if (t > 0) {
            // ---- S1 + S4 fused: a = tanh(h@Whp+bhp); r = h@Wr1+br1 ----
            u64 acc_a[2], acc_r[2];
            acc_a[0] = acc_a[1] = dup2(bias_s[cc]);
            acc_r[0] = acc_r[1] = dup2(bias_s[64 + cc]);
            gemm_pipe<16, true>(g_h + hbase, Whp_p, Wr1_p, bufs,
                                acc_a, acc_r, aoff, woff);
            size_t acol = catbase + (size_t)(c0 + cc) * 64;
            #pragma unroll
            for (int p = 0; p < 2; p++) {
                float2 f = unpack2(acc_a[p]);
                *(float2*)(g_cat + acol + (plbase + p) * 2)
                    = make_float2(tanhf(f.x), tanhf(f.y));
            }
            // S4 partial: v[row] = sum_cols relu(r)*Wr2[col]
            float w2 = bias_s[80 + cc];
            float2 r0 = unpack2(acc_r[0]), r1 = unpack2(acc_r[1]);
            float v0 = fmaxf(r0.x, 0.f) * w2;
            float v1 = fmaxf(r0.y, 0.f) * w2;
            float v2 = fmaxf(r1.x, 0.f) * w2;
            float v3 = fmaxf(r1.y, 0.f) * w2;
            #pragma unroll
            for (int off = 1; off <= 2; off <<= 1) {
                v0 += __shfl_xor_sync(0xffffffffu, v0, off);
                v1 += __shfl_xor_sync(0xffffffffu, v1, off);
                v2 += __shfl_xor_sync(0xffffffffu, v2, off);
                v3 += __shfl_xor_sync(0xffffffffu, v3, off);
            }
            if (lc == 0)
                *(float4*)(g_r1p + (size_t)(bj * 4 + wc) * NBATCH + row0 + wr * 32 + lr * 4)
                    = make_float4(v0, v1, v2, v3);
        } else {
            // h0 == 0 -> cat[:,0:256] = tanh(bhp)
            float av = tanhf(bias_s[cc]);
            size_t acol = catbase + (size_t)(c0 + cc) * 64;
            *(float2*)(g_cat + acol + plbase * 2)       = make_float2(av, av);
            *(float2*)(g_cat + acol + (plbase + 1) * 2) = make_float2(av, av);
        }
        grid_barrier();

        // ================= Phase B: m = tanh(cat @ Wm + bm) =================
        // finalize out[t-1] first so its L2 latency overlaps the GEMM
        if (bj == 0 && t > 0 && tid < BM) {
            int n = row0 + tid;
            float s = br2v;
            #pragma unroll 8
            for (int q = 0; q < 64; q++)
                s += __ldcg(&g_r1p[(size_t)q * NBATCH + n]);
            out[(size_t)(t - 1) * NBATCH + n] = s;
        }
        {
            u64 acc[2];
            acc[0] = acc[1] = dup2(bias_s[32 + cc]);
            gemm_pipe<32, false>(g_cat + catbase, Wm_p, Wm_p, bufs,
                                 acc, acc, aoff, woff);
            size_t mcol = hbase + (size_t)(c0 + cc) * 64;
            #pragma unroll
            for (int p = 0; p < 2; p++) {
                float2 f = unpack2(acc[p]);
                *(float2*)(g_m + mcol + (plbase + p) * 2)
                    = make_float2(tanhf(f.x), tanhf(f.y));
            }
        }
        grid_barrier();

        // ================= Phase C: h = tanh(m @ Whpost + bhpost) ============
        {
            u64 acc[2];
            acc[0] = acc[1] = dup2(bias_s[48 + cc]);
            gemm_pipe<16, false>(g_m + hbase, Whpost_p, Whpost_p, bufs,
                                 acc, acc, aoff, woff);
            size_t hcol = hbase + (size_t)(c0 + cc) * 64;
            #pragma unroll
            for (int p = 0; p < 2; p++) {
                float2 f = unpack2(acc[p]);
                *(float2*)(g_h + hcol + (plbase + p) * 2)
                    = make_float2(tanhf(f.x), tanhf(f.y));
            }
        }
        grid_barrier();
    }

    // ================= Epilogue: regressor for final step =================
    {
        u64 acc[2];
        acc[0] = acc[1] = dup2(bias_s[64 + cc]);
        gemm_pipe<16, false>(g_h + hbase, Wr1_p, Wr1_p, bufs, acc, acc, aoff, woff);
        float w2 = bias_s[80 + cc];
        float2 r0 = unpack2(acc[0]), r1 = unpack2(acc[1]);
        float v0 = fmaxf(r0.x, 0.f) * w2;
        float v1 = fmaxf(r0.y, 0.f) * w2;
        float v2 = fmaxf(r1.x, 0.f) * w2;
        float v3 = fmaxf(r1.y, 0.f) * w2;
        #pragma unroll
        for (int off = 1; off <= 2; off <<= 1) {
            v0 += __shfl_xor_sync(0xffffffffu, v0, off);
            v1 += __shfl_xor_sync(0xffffffffu, v1, off);
            v2 += __shfl_xor_sync(0xffffffffu, v2, off);
            v3 += __shfl_xor_sync(0xffffffffu, v3, off);
        }
        if (lc == 0)
            *(float4*)(g_r1p + (size_t)(bj * 4 + wc) * NBATCH + row0 + wr * 32 + lr * 4)
                = make_float4(v0, v1, v2, v3);
    }
    grid_barrier();
    if (bj == 0 && tid < BM) {
        int n = row0 + tid;
        float s = br2v;
        #pragma unroll 8
        for (int q = 0; q < 64; q++)
            s += __ldcg(&g_r1p[(size_t)q * NBATCH + n]);
        out[(size_t)(T_STEPS - 1) * NBATCH + n] = s;
    }
}

extern "C" void kernel_launch(void* const* d_in, const int* in_sizes, int n_in,
                              void* d_out, int out_size)
{
    (void)in_sizes; (void)n_in; (void)out_size;
    const float* inputs = (const float*)d_in[0];
    const float* Whp    = (const float*)d_in[1];
    const float* bhp    = (const float*)d_in[2];
    const float* Wcp    = (const float*)d_in[3];
    const float* bcp    = (const float*)d_in[4];
    const float* Wm     = (const float*)d_in[5];
    const float* bm     = (const float*)d_in[6];
    const float* Whpost = (const float*)d_in[7];
    const float* bhpost = (const float*)d_in[8];
    const float* Wr1    = (const float*)d_in[9];
    const float* br1    = (const float*)d_in[10];
    const float* Wr2    = (const float*)d_in[11];
    const float* br2    = (const float*)d_in[12];
    float* out = (float*)d_out;

    // smem: packed weights 21504 + bias 128 + 4x1024 staging = 25728 floats
    //     = 102,912 B per CTA -> 2 CTAs/SM (205.8 KB of 228 KB)
    const size_t smem_bytes = (size_t)25728 * sizeof(float);
    cudaFuncSetAttribute(recurrent_kernel,
                         cudaFuncAttributeMaxDynamicSharedMemorySize,
                         (int)smem_bytes);

    recurrent_kernel<<<NCTA, NTHR, smem_bytes>>>(
        inputs, Whp, bhp, Wcp, bcp, Wm, bm, Whpost, bhpost,
        Wr1, br1, Wr2, br2, out);
}

// round 8
// speedup vs baseline: 1.0541x; 1.0541x over previous
#include <cuda_runtime.h>
#include <math.h>
#include <stdint.h>

// Problem constants
#define T_STEPS 512
#define NBATCH  1024
#define IDIM    64
#define RDIM    256
#define NCTA    256
#define NTHR    256
#define BM      64   // batch rows per CTA
#define BN      16   // output cols per CTA

typedef unsigned long long u64;

// -------- global scratch --------
// Activations in per-row-tile k-major pair-packed layout:
//   elem(tile bi, k, row r=2*pl+e) at base(bi) + k*64 + pl*2 + e
__device__ float g_h[NBATCH * RDIM];        // [16][256][32][2]
__device__ float g_cat[NBATCH * 2 * RDIM];  // [16][512][32][2]
__device__ float g_m[NBATCH * RDIM];        // [16][256][32][2]
__device__ float g_r1p[64 * NBATCH];        // regressor partials [bj*4+wc][1024]
__device__ unsigned g_bar_count = 0;
__device__ unsigned g_bar_gen = 0;

// -------- packed f32x2 helpers --------
__device__ __forceinline__ u64 dup2(float w) {
    u64 r; asm("mov.b64 %0, {%1, %1};" : "=l"(r) : "f"(w)); return r;
}
__device__ __forceinline__ void ffma2(u64& d, u64 a, u64 b) {
    asm("fma.rn.f32x2 %0, %1, %2, %0;" : "+l"(d) : "l"(a), "l"(b));
}
__device__ __forceinline__ float2 unpack2(u64 v) {
    float2 f; asm("mov.b64 {%0, %1}, %2;" : "=f"(f.x), "=f"(f.y) : "l"(v)); return f;
}

// -------- cp.async helpers (L1-bypass for cross-CTA coherence) --------
__device__ __forceinline__ void cp_async16(float* sdst, const float* gsrc) {
    unsigned s = (unsigned)__cvta_generic_to_shared(sdst);
    asm volatile("cp.async.cg.shared.global [%0], [%1], 16;" :: "r"(s), "l"(gsrc));
}
__device__ __forceinline__ void cp_commit() { asm volatile("cp.async.commit_group;"); }
template <int N>
__device__ __forceinline__ void cp_wait() {
    asm volatile("cp.async.wait_group %0;" :: "n"(N));
}

// -------- grid-wide sense-reversing barrier --------
__device__ __forceinline__ void grid_barrier() {
    __threadfence();
    __syncthreads();
    if (threadIdx.x == 0) {
        unsigned g = *((volatile unsigned*)&g_bar_gen);
        unsigned old = atomicAdd(&g_bar_count, 1u);
        if (old == NCTA - 1) {
            g_bar_count = 0;
            __threadfence();
            *((volatile unsigned*)&g_bar_gen) = g + 1;
        } else {
            unsigned cur;
            do {
                asm volatile("ld.acquire.gpu.global.u32 %0, [%1];"
                             : "=r"(cur) : "l"(&g_bar_gen));
            } while (cur == g);
        }
    }
    __syncthreads();
}

// -------- stage one contiguous 4KB chunk (16k x 64 floats), one group --------
__device__ __forceinline__ void stage1k(float* buf, const float* __restrict__ g) {
    cp_async16(buf + threadIdx.x * 4, g + threadIdx.x * 4);
    cp_commit();
}

// -------- compute one staged 16k chunk --------
// As: [16 k][64 floats]. Thread: pairs plbase, plbase+1 x 1 col.
// acc: a[0] = pair plbase (2 rows packed), a[1] = pair plbase+1.
template <bool FUSE2>
__device__ __forceinline__ void compute_chunk(
    const float* __restrict__ As,
    const float* __restrict__ w1, const float* __restrict__ w2,
    u64 a1[2], u64 a2[2], int aoff, int woff)
{
    #pragma unroll
    for (int k2 = 0; k2 < 8; k2++) {
        ulonglong2 A0 = *(const ulonglong2*)(As + k2 * 128 + aoff);       // k even
        ulonglong2 A1 = *(const ulonglong2*)(As + k2 * 128 + 64 + aoff);  // k odd
        float2 w = *(const float2*)(w1 + k2 * 32 + woff);
        u64 w0 = dup2(w.x), w1d = dup2(w.y);
        ffma2(a1[0], A0.x, w0);  ffma2(a1[1], A0.y, w0);
        ffma2(a1[0], A1.x, w1d); ffma2(a1[1], A1.y, w1d);
        if constexpr (FUSE2) {
            float2 v = *(const float2*)(w2 + k2 * 32 + woff);
            u64 v0 = dup2(v.x), v1 = dup2(v.y);
            ffma2(a2[0], A0.x, v0); ffma2(a2[1], A0.y, v0);
            ffma2(a2[0], A1.x, v1); ffma2(a2[1], A1.y, v1);
        }
    }
}

// -------- pipelined GEMM over NCH 16k chunks (4-buffer ring, 1 sync/chunk) ---
template <int NCH, bool FUSE2>
__device__ __forceinline__ void gemm_pipe(
    const float* __restrict__ gbase,
    const float* __restrict__ W1, const float* __restrict__ W2,
    float* bufs, u64 a1[2], u64 a2[2], int aoff, int woff)
{
    stage1k(bufs,        gbase);
    stage1k(bufs + 1024, gbase + 1024);
    stage1k(bufs + 2048, gbase + 2048);
    for (int i = 0; i < NCH; i++) {
        if (i + 2 < NCH)      { cp_wait<2>(); }
        else if (i + 1 < NCH) { cp_wait<1>(); }
        else                  { cp_wait<0>(); }
        __syncthreads();
        if (i + 3 < NCH) stage1k(bufs + ((i + 3) & 3) * 1024, gbase + (i + 3) * 1024);
        compute_chunk<FUSE2>(bufs + (i & 3) * 1024, W1 + i * 256, W2 + i * 256,
                             a1, a2, aoff, woff);
    }
}

__global__ void __launch_bounds__(NTHR, 2)
recurrent_kernel(const float* __restrict__ inputs,
                 const float* __restrict__ Whp, const float* __restrict__ bhp,
                 const float* __restrict__ Wcp, const float* __restrict__ bcp,
                 const float* __restrict__ Wm,  const float* __restrict__ bm,
                 const float* __restrict__ Whpost, const float* __restrict__ bhpost,
                 const float* __restrict__ Wr1, const float* __restrict__ br1,
                 const float* __restrict__ Wr2, const float* __restrict__ br2,
                 float* __restrict__ out)
{
    extern __shared__ float smem[];
    float* Whp_p    = smem;                 // 4096 (256k x 16c packed)
    float* Wr1_p    = Whp_p    + 4096;      // 4096
    float* Whpost_p = Wr1_p    + 4096;      // 4096
    float* Wm_p     = Whpost_p + 4096;      // 8192 (512k x 16c)
    float* Wcp_p    = Wm_p     + 8192;      // 1024 (64k x 16c)
    float* bias_s   = Wcp_p    + 1024;      // 128
    float* bufs     = bias_s   + 128;       // 4 x 1024

    const int tid  = threadIdx.x;
    const int wid  = tid >> 5;
    const int lane = tid & 31;
    const int wr = wid & 1;          // row half (32 rows)
    const int wc = wid >> 1;         // col group 0..3 (4 cols each)
    const int lr = lane >> 2;        // lane row 0..7
    const int lc = lane & 3;         // lane col 0..3
    const int plbase = wr * 16 + lr * 2;   // first local pair (of 2)
    const int cc     = wc * 4 + lc;        // local col 0..15
    const int aoff   = plbase * 2;
    const int woff   = cc * 2;

    const int bi   = blockIdx.x >> 4;   // row tile 0..15
    const int bj   = blockIdx.x & 15;   // col tile 0..15
    const int row0 = bi * BM;
    const int c0   = bj * BN;

    const int hbase   = bi * (RDIM * BM);       // 16384 floats per tile
    const int catbase = bi * (2 * RDIM * BM);   // 32768

    // ---- build packed weight slices: Wp[(k>>1)*32 + col*2 + (k&1)] ----
    for (int i = tid; i < 256 * BN; i += NTHR) {
        int k = i >> 4, col = i & 15;
        int d = (k >> 1) * 32 + col * 2 + (k & 1);
        Whp_p[d]    = Whp[k * RDIM + c0 + col];
        Wr1_p[d]    = Wr1[k * RDIM + c0 + col];
        Whpost_p[d] = Whpost[k * RDIM + c0 + col];
    }
    for (int i = tid; i < 512 * BN; i += NTHR) {
        int k = i >> 4, col = i & 15;
        Wm_p[(k >> 1) * 32 + col * 2 + (k & 1)] = Wm[k * RDIM + c0 + col];
    }
    for (int i = tid; i < 64 * BN; i += NTHR) {
        int k = i >> 4, col = i & 15;
        Wcp_p[(k >> 1) * 32 + col * 2 + (k & 1)] = Wcp[k * RDIM + c0 + col];
    }
    if (tid < 16) {
        bias_s[tid]      = bhp[c0 + tid];
        bias_s[16 + tid] = bcp[c0 + tid];
        bias_s[32 + tid] = bm[c0 + tid];
        bias_s[48 + tid] = bhpost[c0 + tid];
        bias_s[64 + tid] = br1[c0 + tid];
        bias_s[80 + tid] = Wr2[c0 + tid];
    }
    const float br2v = __ldg(br2);
    __syncthreads();

    for (int t = 0; t < T_STEPS; t++) {
        // ================= Phase A =================
        // ---- stage x_t (row-major, XOR-swizzled 16B slots) into all 4 bufs --
        {
            const float* xg = inputs + (size_t)t * NBATCH * IDIM + (size_t)row0 * IDIM;
            #pragma unroll
            for (int i2 = 0; i2 < 4; i2++) {
                int u = tid + i2 * NTHR;
                int r = u >> 4, s = u & 15;
                cp_async16(bufs + r * 64 + ((s ^ ((r >> 2) & 7)) << 2),
                           xg + r * 64 + s * 4);
            }
            cp_commit();
            cp_wait<0>();
            __syncthreads();
        }
        // ---- S0: tcp = tanh(x @ Wcp + bcp) -> cat[:, 256:512] ----
        {
            float aS[4];
            #pragma unroll
            for (int j = 0; j < 4; j++) aS[j] = bias_s[16 + cc];
            #pragma unroll 4
            for (int k4 = 0; k4 < 16; k4++) {
                float2 wA = *(const float2*)(Wcp_p + (2 * k4) * 32 + woff);
                float2 wB = *(const float2*)(Wcp_p + (2 * k4 + 1) * 32 + woff);
                #pragma unroll
                for (int j = 0; j < 4; j++) {
                    int r = wr * 32 + lr * 4 + j;
                    float4 a = *(const float4*)(bufs + r * 64 + ((k4 ^ ((r >> 2) & 7)) << 2));
                    aS[j] = fmaf(a.x, wA.x, aS[j]);
                    aS[j] = fmaf(a.y, wA.y, aS[j]);
                    aS[j] = fmaf(a.z, wB.x, aS[j]);
                    aS[j] = fmaf(a.w, wB.y, aS[j]);
                }
            }
            size_t xcol = catbase + (size_t)(RDIM + c0 + cc) * 64;
            *(float2*)(g_cat + xcol + plbase * 2)
                = make_float2(tanhf(aS[0]), tanhf(aS[1]));
            *(float2*)(g_cat + xcol + (plbase + 1) * 2)
                = make_float2(tanhf(aS[2]), tanhf(aS[3]));
            __syncthreads();   // bufs reused by the h pipeline below
        }

        if (t > 0) {
            // ---- S1 + S4 fused: a = tanh(h@Whp+bhp); r = h@Wr1+br1 ----
            u64 acc_a[2], acc_r[2];
            acc_a[0] = acc_a[1] = dup2(bias_s[cc]);
            acc_r[0] = acc_r[1] = dup2(bias_s[64 + cc]);
            gemm_pipe<16, true>(g_h + hbase, Whp_p, Wr1_p, bufs,
                                acc_a, acc_r, aoff, woff);
            size_t acol = catbase + (size_t)(c0 + cc) * 64;
            #pragma unroll
            for (int p = 0; p < 2; p++) {
                float2 f = unpack2(acc_a[p]);
                *(float2*)(g_cat + acol + (plbase + p) * 2)
                    = make_float2(tanhf(f.x), tanhf(f.y));
            }
            // S4 partial: v[row] = sum_cols relu(r)*Wr2[col]
            float w2 = bias_s[80 + cc];
            float2 r0 = unpack2(acc_r[0]), r1 = unpack2(acc_r[1]);
            float v0 = fmaxf(r0.x, 0.f) * w2;
            float v1 = fmaxf(r0.y, 0.f) * w2;
            float v2 = fmaxf(r1.x, 0.f) * w2;
            float v3 = fmaxf(r1.y, 0.f) * w2;
            #pragma unroll
            for (int off = 1; off <= 2; off <<= 1) {
                v0 += __shfl_xor_sync(0xffffffffu, v0, off);
                v1 += __shfl_xor_sync(0xffffffffu, v1, off);
                v2 += __shfl_xor_sync(0xffffffffu, v2, off);
                v3 += __shfl_xor_sync(0xffffffffu, v3, off);
            }
            if (lc == 0)
                *(float4*)(g_r1p + (size_t)(bj * 4 + wc) * NBATCH + row0 + wr * 32 + lr * 4)
                    = make_float4(v0, v1, v2, v3);
        } else {
            // h0 == 0 -> cat[:,0:256] = tanh(bhp)
            float av = tanhf(bias_s[cc]);
            size_t acol = catbase + (size_t)(c0 + cc) * 64;
            *(float2*)(g_cat + acol + plbase * 2)       = make_float2(av, av);
            *(float2*)(g_cat + acol + (plbase + 1) * 2) = make_float2(av, av);
        }
        grid_barrier();

        // ================= Phase B: m = tanh(cat @ Wm + bm) =================
        // finalize out[t-1] first so its L2 latency overlaps the GEMM
        if (bj == 0 && t > 0 && tid < BM) {
            int n = row0 + tid;
            float s = br2v;
            #pragma unroll 8
            for (int q = 0; q < 64; q++)
                s += __ldcg(&g_r1p[(size_t)q * NBATCH + n]);
            out[(size_t)(t - 1) * NBATCH + n] = s;
        }
        {
            u64 acc[2];
            acc[0] = acc[1] = dup2(bias_s[32 + cc]);
            gemm_pipe<32, false>(g_cat + catbase, Wm_p, Wm_p, bufs,
                                 acc, acc, aoff, woff);
            size_t mcol = hbase + (size_t)(c0 + cc) * 64;
            #pragma unroll
            for (int p = 0; p < 2; p++) {
                float2 f = unpack2(acc[p]);
                *(float2*)(g_m + mcol + (plbase + p) * 2)
                    = make_float2(tanhf(f.x), tanhf(f.y));
            }
        }
        grid_barrier();

        // ================= Phase C: h = tanh(m @ Whpost + bhpost) ============
        {
            u64 acc[2];
            acc[0] = acc[1] = dup2(bias_s[48 + cc]);
            gemm_pipe<16, false>(g_m + hbase, Whpost_p, Whpost_p, bufs,
                                 acc, acc, aoff, woff);
            size_t hcol = hbase + (size_t)(c0 + cc) * 64;
            #pragma unroll
            for (int p = 0; p < 2; p++) {
                float2 f = unpack2(acc[p]);
                *(float2*)(g_h + hcol + (plbase + p) * 2)
                    = make_float2(tanhf(f.x), tanhf(f.y));
            }
        }
        grid_barrier();
    }

    // ================= Epilogue: regressor for final step =================
    {
        u64 acc[2];
        acc[0] = acc[1] = dup2(bias_s[64 + cc]);
        gemm_pipe<16, false>(g_h + hbase, Wr1_p, Wr1_p, bufs, acc, acc, aoff, woff);
        float w2 = bias_s[80 + cc];
        float2 r0 = unpack2(acc[0]), r1 = unpack2(acc[1]);
        float v0 = fmaxf(r0.x, 0.f) * w2;
        float v1 = fmaxf(r0.y, 0.f) * w2;
        float v2 = fmaxf(r1.x, 0.f) * w2;
        float v3 = fmaxf(r1.y, 0.f) * w2;
        #pragma unroll
        for (int off = 1; off <= 2; off <<= 1) {
            v0 += __shfl_xor_sync(0xffffffffu, v0, off);
            v1 += __shfl_xor_sync(0xffffffffu, v1, off);
            v2 += __shfl_xor_sync(0xffffffffu, v2, off);
            v3 += __shfl_xor_sync(0xffffffffu, v3, off);
        }
        if (lc == 0)
            *(float4*)(g_r1p + (size_t)(bj * 4 + wc) * NBATCH + row0 + wr * 32 + lr * 4)
                = make_float4(v0, v1, v2, v3);
    }
    grid_barrier();
    if (bj == 0 && tid < BM) {
        int n = row0 + tid;
        float s = br2v;
        #pragma unroll 8
        for (int q = 0; q < 64; q++)
            s += __ldcg(&g_r1p[(size_t)q * NBATCH + n]);
        out[(size_t)(T_STEPS - 1) * NBATCH + n] = s;
    }
}

extern "C" void kernel_launch(void* const* d_in, const int* in_sizes, int n_in,
                              void* d_out, int out_size)
{
    (void)in_sizes; (void)n_in; (void)out_size;
    const float* inputs = (const float*)d_in[0];
    const float* Whp    = (const float*)d_in[1];
    const float* bhp    = (const float*)d_in[2];
    const float* Wcp    = (const float*)d_in[3];
    const float* bcp    = (const float*)d_in[4];
    const float* Wm     = (const float*)d_in[5];
    const float* bm     = (const float*)d_in[6];
    const float* Whpost = (const float*)d_in[7];
    const float* bhpost = (const float*)d_in[8];
    const float* Wr1    = (const float*)d_in[9];
    const float* br1    = (const float*)d_in[10];
    const float* Wr2    = (const float*)d_in[11];
    const float* br2    = (const float*)d_in[12];
    float* out = (float*)d_out;

    // smem: packed weights 21504 + bias 128 + 4x1024 staging = 25728 floats
    //     = 102,912 B per CTA -> 2 CTAs/SM (205.8 KB of 228 KB)
    const size_t smem_bytes = (size_t)25728 * sizeof(float);
    cudaFuncSetAttribute(recurrent_kernel,
                         cudaFuncAttributeMaxDynamicSharedMemorySize,
                         (int)smem_bytes);

    recurrent_kernel<<<NCTA, NTHR, smem_bytes>>>(
        inputs, Whp, bhp, Wcp, bcp, Wm, bm, Whpost, bhpost,
        Wr1, br1, Wr2, br2, out);
}

// round 9
// speedup vs baseline: 1.5058x; 1.4286x over previous
#include <cuda_runtime.h>
#include <math.h>
#include <stdint.h>

// Problem constants
#define T_STEPS 512
#define NBATCH  1024
#define IDIM    64
#define RDIM    256
#define NCTA    128
#define NTHR    512
#define BM      64   // batch rows per CTA
#define BN      32   // output cols per CTA

typedef unsigned long long u64;

// -------- global scratch --------
// Activations in per-row-tile k-major pair-packed layout:
//   elem(tile bi, k, row r=2*pl+e) at base(bi) + k*64 + pl*2 + e
__device__ float g_h[NBATCH * RDIM];        // [16][256][32][2]
__device__ float g_cat[NBATCH * 2 * RDIM];  // [16][512][32][2]
__device__ float g_m[NBATCH * RDIM];        // [16][256][32][2]
__device__ float g_r1p[32 * NBATCH];        // regressor partials [bj*4+wc][1024]
__device__ unsigned g_bar_count = 0;
__device__ unsigned g_bar_gen = 0;

// -------- packed f32x2 helpers --------
__device__ __forceinline__ u64 dup2(float w) {
    u64 r; asm("mov.b64 %0, {%1, %1};" : "=l"(r) : "f"(w)); return r;
}
__device__ __forceinline__ void ffma2(u64& d, u64 a, u64 b) {
    asm("fma.rn.f32x2 %0, %1, %2, %0;" : "+l"(d) : "l"(a), "l"(b));
}
__device__ __forceinline__ void fadd2(u64& d, u64 o) {
    asm("add.rn.f32x2 %0, %0, %1;" : "+l"(d) : "l"(o));
}
__device__ __forceinline__ float2 unpack2(u64 v) {
    float2 f; asm("mov.b64 {%0, %1}, %2;" : "=f"(f.x), "=f"(f.y) : "l"(v)); return f;
}

// -------- cp.async helpers (L1-bypass for cross-CTA coherence) --------
__device__ __forceinline__ void cp_async16(float* sdst, const float* gsrc) {
    unsigned s = (unsigned)__cvta_generic_to_shared(sdst);
    asm volatile("cp.async.cg.shared.global [%0], [%1], 16;" :: "r"(s), "l"(gsrc));
}
__device__ __forceinline__ void cp_commit() { asm volatile("cp.async.commit_group;"); }
template <int N>
__device__ __forceinline__ void cp_wait() {
    asm volatile("cp.async.wait_group %0;" :: "n"(N));
}

// -------- grid-wide sense-reversing barrier --------
__device__ __forceinline__ void grid_barrier() {
    __threadfence();
    __syncthreads();
    if (threadIdx.x == 0) {
        unsigned g = *((volatile unsigned*)&g_bar_gen);
        unsigned old = atomicAdd(&g_bar_count, 1u);
        if (old == NCTA - 1) {
            g_bar_count = 0;
            __threadfence();
            *((volatile unsigned*)&g_bar_gen) = g + 1;
        } else {
            unsigned cur;
            do {
                asm volatile("ld.acquire.gpu.global.u32 %0, [%1];"
                             : "=r"(cur) : "l"(&g_bar_gen));
            } while (cur == g);
        }
    }
    __syncthreads();
}

// -------- stage one contiguous 16KB chunk (64k x 64 floats), one group ------
__device__ __forceinline__ void stage16k(float* buf, const float* __restrict__ g) {
    int u = threadIdx.x;
    #pragma unroll
    for (int i = 0; i < 2; i++, u += NTHR)
        cp_async16(buf + u * 4, g + u * 4);
    cp_commit();
}

// -------- compute this team's half (32 k) of a staged 64-k chunk -----------
// As: [k][pair][e]. Thread: 2 pairs x 2 cols. acc: p0c0, p1c0, p0c1, p1c1.
template <bool FUSE2>
__device__ __forceinline__ void compute_chunk(
    const float* __restrict__ As,      // + team*2048 applied by caller
    const float* __restrict__ w1p,     // + team*1024 applied by caller
    const float* __restrict__ w2p,
    u64 a1[4], u64 a2[4], int aoff, int cc2)
{
    #pragma unroll 8
    for (int k2 = 0; k2 < 16; k2++) {
        const float* arow = As + k2 * 128 + aoff;
        ulonglong2 A0 = *(const ulonglong2*)(arow);        // k even: 2 pairs
        ulonglong2 A1 = *(const ulonglong2*)(arow + 64);   // k odd
        float4 w = *(const float4*)(w1p + k2 * 64 + cc2);
        u64 w00 = dup2(w.x), w01 = dup2(w.y), w10 = dup2(w.z), w11 = dup2(w.w);
        ffma2(a1[0], A0.x, w00); ffma2(a1[1], A0.y, w00);
        ffma2(a1[2], A0.x, w10); ffma2(a1[3], A0.y, w10);
        ffma2(a1[0], A1.x, w01); ffma2(a1[1], A1.y, w01);
        ffma2(a1[2], A1.x, w11); ffma2(a1[3], A1.y, w11);
        if constexpr (FUSE2) {
            float4 v = *(const float4*)(w2p + k2 * 64 + cc2);
            u64 v00 = dup2(v.x), v01 = dup2(v.y), v10 = dup2(v.z), v11 = dup2(v.w);
            ffma2(a2[0], A0.x, v00); ffma2(a2[1], A0.y, v00);
            ffma2(a2[2], A0.x, v10); ffma2(a2[3], A0.y, v10);
            ffma2(a2[0], A1.x, v01); ffma2(a2[1], A1.y, v01);
            ffma2(a2[2], A1.x, v11); ffma2(a2[3], A1.y, v11);
        }
    }
}

// -------- pipelined GEMM over NCH 64k chunks (3-buffer ring, 1 sync/chunk) --
template <int NCH, bool FUSE2>
__device__ __forceinline__ void gemm_pipe(
    const float* __restrict__ gbase,
    const float* __restrict__ W1, const float* __restrict__ W2,
    float* bufs, u64 a1[4], u64 a2[4], int aoff, int cc2, int team)
{
    const int koffA = team * 2048;   // 16 k2-windows * 128 floats
    const int koffW = team * 1024;   // 16 k2-windows * 64 floats
    stage16k(bufs,        gbase);
    stage16k(bufs + 4096, gbase + 4096);
    #pragma unroll
    for (int i = 0; i < NCH; i++) {
        if (i < NCH - 1) cp_wait<1>(); else cp_wait<0>();
        __syncthreads();
        if (i + 2 < NCH) stage16k(bufs + ((i + 2) % 3) * 4096, gbase + (i + 2) * 4096);
        compute_chunk<FUSE2>(bufs + (i % 3) * 4096 + koffA,
                             W1 + i * 2048 + koffW, W2 + i * 2048 + koffW,
                             a1, a2, aoff, cc2);
    }
}

// -------- team partial-sum reduction through an idle smem ring slot ---------
template <int N>
__device__ __forceinline__ void team_reduce(u64* acc, float* redf, int team, int tidB)
{
    u64* red = (u64*)redf;
    if (team) {
        #pragma unroll
        for (int j = 0; j < N; j++) red[j * 256 + tidB] = acc[j];
    }
    __syncthreads();
    if (!team) {
        #pragma unroll
        for (int j = 0; j < N; j++) fadd2(acc[j], red[j * 256 + tidB]);
    }
    __syncthreads();
}

__global__ void __launch_bounds__(NTHR, 1)
recurrent_kernel(const float* __restrict__ inputs,
                 const float* __restrict__ Whp, const float* __restrict__ bhp,
                 const float* __restrict__ Wcp, const float* __restrict__ bcp,
                 const float* __restrict__ Wm,  const float* __restrict__ bm,
                 const float* __restrict__ Whpost, const float* __restrict__ bhpost,
                 const float* __restrict__ Wr1, const float* __restrict__ br1,
                 const float* __restrict__ Wr2, const float* __restrict__ br2,
                 float* __restrict__ out)
{
    extern __shared__ float smem[];
    float* Whp_p    = smem;                 // 8192  (256k packed)
    float* Wr1_p    = Whp_p    + 8192;      // 8192
    float* Wm_p     = Wr1_p    + 8192;      // 16384 (512k packed)
    float* Whpost_p = Wm_p     + 16384;     // 8192
    float* Wcp_p    = Whpost_p + 8192;      // 2048  (64k packed)
    float* bias_s   = Wcp_p    + 2048;      // 192
    float* bufs     = bias_s   + 192;       // 3 x 4096

    const int tid  = threadIdx.x;
    const int team = tid >> 8;         // 0 or 1 (k-split team)
    const int tidB = tid & 255;        // index within team
    const int wid8 = tidB >> 5;        // team-local warp 0..7
    const int lane = tid & 31;
    const int wr = wid8 & 1;           // row half (32 rows)
    const int wc = wid8 >> 1;          // col group 0..3 (8 cols each)
    const int lr = lane >> 2;          // lane row 0..7
    const int lc = lane & 3;           // lane col 0..3
    const int plbase = wr * 16 + lr * 2;   // first local pair (of 2)
    const int cc     = wc * 8 + lc * 2;    // first local col (of 2)
    const int aoff   = plbase * 2;
    const int cc2    = cc * 2;

    const int bi   = blockIdx.x >> 3;   // row tile 0..15
    const int bj   = blockIdx.x & 7;    // col tile 0..7
    const int row0 = bi * BM;
    const int c0   = bj * BN;

    const int hbase   = bi * (RDIM * BM);       // 16384 floats per tile
    const int catbase = bi * (2 * RDIM * BM);   // 32768

    // ---- build packed weight slices: Wp[(k>>1)*64 + col*2 + (k&1)] ----
    for (int i = tid; i < 256 * BN; i += NTHR) {
        int k = i >> 5, col = i & 31;
        int d = (k >> 1) * 64 + col * 2 + (k & 1);
        Whp_p[d]    = Whp[k * RDIM + c0 + col];
        Wr1_p[d]    = Wr1[k * RDIM + c0 + col];
        Whpost_p[d] = Whpost[k * RDIM + c0 + col];
    }
    for (int i = tid; i < 512 * BN; i += NTHR) {
        int k = i >> 5, col = i & 31;
        Wm_p[(k >> 1) * 64 + col * 2 + (k & 1)] = Wm[k * RDIM + c0 + col];
    }
    for (int i = tid; i < 64 * BN; i += NTHR) {
        int k = i >> 5, col = i & 31;
        Wcp_p[(k >> 1) * 64 + col * 2 + (k & 1)] = Wcp[k * RDIM + c0 + col];
    }
    if (tid < 32) {
        bias_s[tid]       = bhp[c0 + tid];
        bias_s[32 + tid]  = bcp[c0 + tid];
        bias_s[64 + tid]  = bm[c0 + tid];
        bias_s[96 + tid]  = bhpost[c0 + tid];
        bias_s[128 + tid] = br1[c0 + tid];
        bias_s[160 + tid] = Wr2[c0 + tid];
    }
    const float br2v = __ldg(br2);
    __syncthreads();

    for (int t = 0; t < T_STEPS; t++) {
        // ================= Phase A =================
        // ---- stage x_t (row-major, XOR-swizzled 16B slots) into buf0 ----
        {
            const float* xg = inputs + (size_t)t * NBATCH * IDIM + (size_t)row0 * IDIM;
            int u = tid;
            #pragma unroll
            for (int i = 0; i < 2; i++, u += NTHR) {
                int r = u >> 4, s = u & 15;
                cp_async16(bufs + r * 64 + ((s ^ ((r >> 2) & 7)) << 2),
                           xg + r * 64 + s * 4);
            }
            cp_commit();
            cp_wait<0>();
            __syncthreads();
        }
        // ---- S0: tcp = tanh(x @ Wcp + bcp), team-split over k ----
        {
            float aS[4];
            #pragma unroll
            for (int j = 0; j < 4; j++) aS[j] = team ? 0.f : bias_s[16 + cc - cc + 32 + cc] * 0.f + bias_s[32 + cc];
            // (team A carries bias; team B starts at 0)
            if (team) { aS[0] = aS[1] = aS[2] = aS[3] = 0.f; }
            else { aS[0] = aS[1] = bias_s[32 + cc]; aS[2] = aS[3] = bias_s[32 + cc + 1]; }
            // aS layout: [0]=row j0 c0, [1]=row j1 c0 ... use [rowj][col] flattened below
            float aT[4][2];
            #pragma unroll
            for (int j = 0; j < 4; j++) {
                aT[j][0] = team ? 0.f : bias_s[32 + cc];
                aT[j][1] = team ? 0.f : bias_s[32 + cc + 1];
            }
            #pragma unroll
            for (int k4i = 0; k4i < 8; k4i++) {
                int k4 = team * 8 + k4i;
                float4 wA = *(const float4*)(Wcp_p + (2 * k4) * 64 + cc2);
                float4 wB = *(const float4*)(Wcp_p + (2 * k4 + 1) * 64 + cc2);
                #pragma unroll
                for (int j = 0; j < 4; j++) {
                    int r = wr * 32 + lr * 4 + j;
                    float4 a = *(const float4*)(bufs + r * 64 + ((k4 ^ ((r >> 2) & 7)) << 2));
                    aT[j][0] = fmaf(a.x, wA.x, aT[j][0]);
                    aT[j][0] = fmaf(a.y, wA.y, aT[j][0]);
                    aT[j][0] = fmaf(a.z, wB.x, aT[j][0]);
                    aT[j][0] = fmaf(a.w, wB.y, aT[j][0]);
                    aT[j][1] = fmaf(a.x, wA.z, aT[j][1]);
                    aT[j][1] = fmaf(a.y, wA.w, aT[j][1]);
                    aT[j][1] = fmaf(a.z, wB.z, aT[j][1]);
                    aT[j][1] = fmaf(a.w, wB.w, aT[j][1]);
                }
            }
            // reduce team partials through buf1
            float* redf = bufs + 4096;
            if (team) {
                #pragma unroll
                for (int j = 0; j < 4; j++) {
                    redf[(2 * j) * 256 + tidB]     = aT[j][0];
                    redf[(2 * j + 1) * 256 + tidB] = aT[j][1];
                }
            }
            __syncthreads();
            if (!team) {
                #pragma unroll
                for (int j = 0; j < 4; j++) {
                    aT[j][0] += redf[(2 * j) * 256 + tidB];
                    aT[j][1] += redf[(2 * j + 1) * 256 + tidB];
                }
            }
            __syncthreads();
            if (!team) {
                #pragma unroll
                for (int ci = 0; ci < 2; ci++) {
                    size_t xcol = catbase + (size_t)(RDIM + c0 + cc + ci) * 64;
                    *(float2*)(g_cat + xcol + plbase * 2)
                        = make_float2(tanhf(aT[0][ci]), tanhf(aT[1][ci]));
                    *(float2*)(g_cat + xcol + (plbase + 1) * 2)
                        = make_float2(tanhf(aT[2][ci]), tanhf(aT[3][ci]));
                }
            }
        }

        if (t > 0) {
            // ---- S1 + S4 fused: a = tanh(h@Whp+bhp); r = h@Wr1+br1 ----
            u64 acc_a[4], acc_r[4];
            if (team) {
                acc_a[0] = acc_a[1] = acc_a[2] = acc_a[3] = 0;
                acc_r[0] = acc_r[1] = acc_r[2] = acc_r[3] = 0;
            } else {
                acc_a[0] = acc_a[1] = dup2(bias_s[cc]);
                acc_a[2] = acc_a[3] = dup2(bias_s[cc + 1]);
                acc_r[0] = acc_r[1] = dup2(bias_s[128 + cc]);
                acc_r[2] = acc_r[3] = dup2(bias_s[128 + cc + 1]);
            }
            gemm_pipe<4, true>(g_h + hbase, Whp_p, Wr1_p, bufs,
                               acc_a, acc_r, aoff, cc2, team);
            // reduce 8 accs through ring slot (4%3)=1
            {
                float* redf = bufs + 4096;
                u64* red = (u64*)redf;
                if (team) {
                    #pragma unroll
                    for (int j = 0; j < 4; j++) {
                        red[j * 256 + tidB]       = acc_a[j];
                        red[(4 + j) * 256 + tidB] = acc_r[j];
                    }
                }
                __syncthreads();
                if (!team) {
                    #pragma unroll
                    for (int j = 0; j < 4; j++) {
                        fadd2(acc_a[j], red[j * 256 + tidB]);
                        fadd2(acc_r[j], red[(4 + j) * 256 + tidB]);
                    }
                }
                __syncthreads();
            }
            if (!team) {
                #pragma unroll
                for (int ci = 0; ci < 2; ci++) {
                    size_t acol = catbase + (size_t)(c0 + cc + ci) * 64;
                    #pragma unroll
                    for (int p = 0; p < 2; p++) {
                        float2 f = unpack2(acc_a[ci * 2 + p]);
                        *(float2*)(g_cat + acol + (plbase + p) * 2)
                            = make_float2(tanhf(f.x), tanhf(f.y));
                    }
                }
                // S4 partial: v[row] = sum_cols relu(r)*Wr2[col]
                float w20 = bias_s[160 + cc], w21 = bias_s[160 + cc + 1];
                float2 r00 = unpack2(acc_r[0]), r10 = unpack2(acc_r[1]);
                float2 r01 = unpack2(acc_r[2]), r11 = unpack2(acc_r[3]);
                float v0 = fmaxf(r00.x, 0.f) * w20 + fmaxf(r01.x, 0.f) * w21;
                float v1 = fmaxf(r00.y, 0.f) * w20 + fmaxf(r01.y, 0.f) * w21;
                float v2 = fmaxf(r10.x, 0.f) * w20 + fmaxf(r11.x, 0.f) * w21;
                float v3 = fmaxf(r10.y, 0.f) * w20 + fmaxf(r11.y, 0.f) * w21;
                #pragma unroll
                for (int off = 1; off <= 2; off <<= 1) {
                    v0 += __shfl_xor_sync(0xffffffffu, v0, off);
                    v1 += __shfl_xor_sync(0xffffffffu, v1, off);
                    v2 += __shfl_xor_sync(0xffffffffu, v2, off);
                    v3 += __shfl_xor_sync(0xffffffffu, v3, off);
                }
                if (lc == 0)
                    *(float4*)(g_r1p + (size_t)(bj * 4 + wc) * NBATCH + row0 + wr * 32 + lr * 4)
                        = make_float4(v0, v1, v2, v3);
            }
        } else if (!team) {
            // h0 == 0 -> cat[:,0:256] = tanh(bhp)
            #pragma unroll
            for (int ci = 0; ci < 2; ci++) {
                float av = tanhf(bias_s[cc + ci]);
                size_t acol = catbase + (size_t)(c0 + cc + ci) * 64;
                *(float2*)(g_cat + acol + plbase * 2)       = make_float2(av, av);
                *(float2*)(g_cat + acol + (plbase + 1) * 2) = make_float2(av, av);
            }
        }
        grid_barrier();

        // ================= Phase B: m = tanh(cat @ Wm + bm) =================
        // finalize out[t-1] first so its L2 latency overlaps the GEMM
        if (bj == 0 && t > 0 && tid < BM) {
            int n = row0 + tid;
            float s = br2v;
            #pragma unroll 8
            for (int q = 0; q < 32; q++)
                s += __ldcg(&g_r1p[(size_t)q * NBATCH + n]);
            out[(size_t)(t - 1) * NBATCH + n] = s;
        }
        {
            u64 acc[4];
            if (team) { acc[0] = acc[1] = acc[2] = acc[3] = 0; }
            else {
                acc[0] = acc[1] = dup2(bias_s[64 + cc]);
                acc[2] = acc[3] = dup2(bias_s[64 + cc + 1]);
            }
            gemm_pipe<8, false>(g_cat + catbase, Wm_p, Wm_p, bufs,
                                acc, acc, aoff, cc2, team);
            team_reduce<4>(acc, bufs + 2 * 4096, team, tidB);   // slot (8%3)=2
            if (!team) {
                #pragma unroll
                for (int ci = 0; ci < 2; ci++) {
                    size_t mcol = hbase + (size_t)(c0 + cc + ci) * 64;
                    #pragma unroll
                    for (int p = 0; p < 2; p++) {
                        float2 f = unpack2(acc[ci * 2 + p]);
                        *(float2*)(g_m + mcol + (plbase + p) * 2)
                            = make_float2(tanhf(f.x), tanhf(f.y));
                    }
                }
            }
        }
        grid_barrier();

        // ================= Phase C: h = tanh(m @ Whpost + bhpost) ============
        {
            u64 acc[4];
            if (team) { acc[0] = acc[1] = acc[2] = acc[3] = 0; }
            else {
                acc[0] = acc[1] = dup2(bias_s[96 + cc]);
                acc[2] = acc[3] = dup2(bias_s[96 + cc + 1]);
            }
            gemm_pipe<4, false>(g_m + hbase, Whpost_p, Whpost_p, bufs,
                                acc, acc, aoff, cc2, team);
            team_reduce<4>(acc, bufs + 4096, team, tidB);       // slot (4%3)=1
            if (!team) {
                #pragma unroll
                for (int ci = 0; ci < 2; ci++) {
                    size_t hcol = hbase + (size_t)(c0 + cc + ci) * 64;
                    #pragma unroll
                    for (int p = 0; p < 2; p++) {
                        float2 f = unpack2(acc[ci * 2 + p]);
                        *(float2*)(g_h + hcol + (plbase + p) * 2)
                            = make_float2(tanhf(f.x), tanhf(f.y));
                    }
                }
            }
        }
        grid_barrier();
    }

    // ================= Epilogue: regressor for final step =================
    {
        u64 acc[4];
        if (team) { acc[0] = acc[1] = acc[2] = acc[3] = 0; }
        else {
            acc[0] = acc[1] = dup2(bias_s[128 + cc]);
            acc[2] = acc[3] = dup2(bias_s[128 + cc + 1]);
        }
        gemm_pipe<4, false>(g_h + hbase, Wr1_p, Wr1_p, bufs, acc, acc, aoff, cc2, team);
        team_reduce<4>(acc, bufs + 4096, team, tidB);
        if (!team) {
            float w20 = bias_s[160 + cc], w21 = bias_s[160 + cc + 1];
            float2 r00 = unpack2(acc[0]), r10 = unpack2(acc[1]);
            float2 r01 = unpack2(acc[2]), r11 = unpack2(acc[3]);
            float v0 = fmaxf(r00.x, 0.f) * w20 + fmaxf(r01.x, 0.f) * w21;
            float v1 = fmaxf(r00.y, 0.f) * w20 + fmaxf(r01.y, 0.f) * w21;
            float v2 = fmaxf(r10.x, 0.f) * w20 + fmaxf(r11.x, 0.f) * w21;
            float v3 = fmaxf(r10.y, 0.f) * w20 + fmaxf(r11.y, 0.f) * w21;
            #pragma unroll
            for (int off = 1; off <= 2; off <<= 1) {
                v0 += __shfl_xor_sync(0xffffffffu, v0, off);
                v1 += __shfl_xor_sync(0xffffffffu, v1, off);
                v2 += __shfl_xor_sync(0xffffffffu, v2, off);
                v3 += __shfl_xor_sync(0xffffffffu, v3, off);
            }
            if (lc == 0)
                *(float4*)(g_r1p + (size_t)(bj * 4 + wc) * NBATCH + row0 + wr * 32 + lr * 4)
                    = make_float4(v0, v1, v2, v3);
        }
    }
    grid_barrier();
    if (bj == 0 && tid < BM) {
        int n = row0 + tid;
        float s = br2v;
        #pragma unroll 8
        for (int q = 0; q < 32; q++)
            s += __ldcg(&g_r1p[(size_t)q * NBATCH + n]);
        out[(size_t)(T_STEPS - 1) * NBATCH + n] = s;
    }
}

extern "C" void kernel_launch(void* const* d_in, const int* in_sizes, int n_in,
                              void* d_out, int out_size)
{
    (void)in_sizes; (void)n_in; (void)out_size;
    const float* inputs = (const float*)d_in[0];
    const float* Whp    = (const float*)d_in[1];
    const float* bhp    = (const float*)d_in[2];
    const float* Wcp    = (const float*)d_in[3];
    const float* bcp    = (const float*)d_in[4];
    const float* Wm     = (const float*)d_in[5];
    const float* bm     = (const float*)d_in[6];
    const float* Whpost = (const float*)d_in[7];
    const float* bhpost = (const float*)d_in[8];
    const float* Wr1    = (const float*)d_in[9];
    const float* br1    = (const float*)d_in[10];
    const float* Wr2    = (const float*)d_in[11];
    const float* br2    = (const float*)d_in[12];
    float* out = (float*)d_out;

    // smem: packed weights 43008 + bias 192 + 3x4096 staging = 55488 floats
    //     = 221,952 B per CTA -> 1 CTA/SM
    const size_t smem_bytes = (size_t)55488 * sizeof(float);
    cudaFuncSetAttribute(recurrent_kernel,
                         cudaFuncAttributeMaxDynamicSharedMemorySize,
                         (int)smem_bytes);

    recurrent_kernel<<<NCTA, NTHR, smem_bytes>>>(
        inputs, Whp, bhp, Wcp, bcp, Wm, bm, Whpost, bhpost,
        Wr1, br1, Wr2, br2, out);
}

// round 11
// speedup vs baseline: 1.5068x; 1.0007x over previous
#include <cuda_runtime.h>
#include <math.h>
#include <stdint.h>

// Problem constants
#define T_STEPS 512
#define NBATCH  1024
#define IDIM    64
#define RDIM    256
#define NCTA    128
#define NTHR    512
#define BM      64   // batch rows per CTA
#define BN      32   // output cols per CTA

typedef unsigned long long u64;

// -------- global scratch --------
// Activations in per-row-tile k-major pair-packed layout:
//   elem(tile bi, k, row r=2*pl+e) at base(bi) + k*64 + pl*2 + e
__device__ float g_h[NBATCH * RDIM];        // [16][256][32][2]
__device__ float g_cat[NBATCH * 2 * RDIM];  // [16][512][32][2]
__device__ float g_m[NBATCH * RDIM];        // [16][256][32][2]
__device__ float g_r1p[32 * NBATCH];        // regressor partials [bj*4+wc][1024]
__device__ unsigned g_bar_count = 0;
__device__ unsigned g_bar_gen = 0;

// -------- packed f32x2 helpers --------
__device__ __forceinline__ u64 dup2(float w) {
    u64 r; asm("mov.b64 %0, {%1, %1};" : "=l"(r) : "f"(w)); return r;
}
__device__ __forceinline__ void ffma2(u64& d, u64 a, u64 b) {
    asm("fma.rn.f32x2 %0, %1, %2, %0;" : "+l"(d) : "l"(a), "l"(b));
}
__device__ __forceinline__ void fadd2(u64& d, u64 o) {
    asm("add.rn.f32x2 %0, %0, %1;" : "+l"(d) : "l"(o));
}
__device__ __forceinline__ float2 unpack2(u64 v) {
    float2 f; asm("mov.b64 {%0, %1}, %2;" : "=f"(f.x), "=f"(f.y) : "l"(v)); return f;
}

// -------- cp.async helpers (L1-bypass for cross-CTA coherence) --------
__device__ __forceinline__ void cp_async16(float* sdst, const float* gsrc) {
    unsigned s = (unsigned)__cvta_generic_to_shared(sdst);
    asm volatile("cp.async.cg.shared.global [%0], [%1], 16;" :: "r"(s), "l"(gsrc));
}
__device__ __forceinline__ void cp_commit() { asm volatile("cp.async.commit_group;"); }
template <int N>
__device__ __forceinline__ void cp_wait() {
    asm volatile("cp.async.wait_group %0;" :: "n"(N));
}

// -------- grid-wide sense-reversing barrier --------
__device__ __forceinline__ void grid_barrier() {
    __threadfence();
    __syncthreads();
    if (threadIdx.x == 0) {
        unsigned g = *((volatile unsigned*)&g_bar_gen);
        unsigned old = atomicAdd(&g_bar_count, 1u);
        if (old == NCTA - 1) {
            g_bar_count = 0;
            __threadfence();
            *((volatile unsigned*)&g_bar_gen) = g + 1;
        } else {
            unsigned cur;
            do {
                asm volatile("ld.acquire.gpu.global.u32 %0, [%1];"
                             : "=r"(cur) : "l"(&g_bar_gen));
            } while (cur == g);
        }
    }
    __syncthreads();
}

// -------- stage one contiguous 16KB chunk (64k x 64 floats), one group ------
__device__ __forceinline__ void stage16k(float* buf, const float* __restrict__ g) {
    int u = threadIdx.x;
    #pragma unroll
    for (int i = 0; i < 2; i++, u += NTHR)
        cp_async16(buf + u * 4, g + u * 4);
    cp_commit();
}

// -------- compute this team's half (32 k) of a staged 64-k chunk -----------
// As: [k][pair][e]. Thread: 2 pairs x 2 cols. acc: p0c0, p1c0, p0c1, p1c1.
template <bool FUSE2>
__device__ __forceinline__ void compute_chunk(
    const float* __restrict__ As,      // + team*2048 applied by caller
    const float* __restrict__ w1p,     // + team*1024 applied by caller
    const float* __restrict__ w2p,
    u64 a1[4], u64 a2[4], int aoff, int cc2)
{
    #pragma unroll 8
    for (int k2 = 0; k2 < 16; k2++) {
        const float* arow = As + k2 * 128 + aoff;
        ulonglong2 A0 = *(const ulonglong2*)(arow);        // k even: 2 pairs
        ulonglong2 A1 = *(const ulonglong2*)(arow + 64);   // k odd
        float4 w = *(const float4*)(w1p + k2 * 64 + cc2);
        u64 w00 = dup2(w.x), w01 = dup2(w.y), w10 = dup2(w.z), w11 = dup2(w.w);
        ffma2(a1[0], A0.x, w00); ffma2(a1[1], A0.y, w00);
        ffma2(a1[2], A0.x, w10); ffma2(a1[3], A0.y, w10);
        ffma2(a1[0], A1.x, w01); ffma2(a1[1], A1.y, w01);
        ffma2(a1[2], A1.x, w11); ffma2(a1[3], A1.y, w11);
        if constexpr (FUSE2) {
            float4 v = *(const float4*)(w2p + k2 * 64 + cc2);
            u64 v00 = dup2(v.x), v01 = dup2(v.y), v10 = dup2(v.z), v11 = dup2(v.w);
            ffma2(a2[0], A0.x, v00); ffma2(a2[1], A0.y, v00);
            ffma2(a2[2], A0.x, v10); ffma2(a2[3], A0.y, v10);
            ffma2(a2[0], A1.x, v01); ffma2(a2[1], A1.y, v01);
            ffma2(a2[2], A1.x, v11); ffma2(a2[3], A1.y, v11);
        }
    }
}

// -------- pipelined GEMM over NCH 64k chunks (3-buffer ring, 1 sync/chunk) --
template <int NCH, bool FUSE2>
__device__ __forceinline__ void gemm_pipe(
    const float* __restrict__ gbase,
    const float* __restrict__ W1, const float* __restrict__ W2,
    float* bufs, u64 a1[4], u64 a2[4], int aoff, int cc2, int team)
{
    const int koffA = team * 2048;   // 16 k2-windows * 128 floats
    const int koffW = team * 1024;   // 16 k2-windows * 64 floats
    stage16k(bufs,        gbase);
    stage16k(bufs + 4096, gbase + 4096);
    #pragma unroll
    for (int i = 0; i < NCH; i++) {
        if (i < NCH - 1) cp_wait<1>(); else cp_wait<0>();
        __syncthreads();
        if (i + 2 < NCH) stage16k(bufs + ((i + 2) % 3) * 4096, gbase + (i + 2) * 4096);
        compute_chunk<FUSE2>(bufs + (i % 3) * 4096 + koffA,
                             W1 + i * 2048 + koffW, W2 + i * 2048 + koffW,
                             a1, a2, aoff, cc2);
    }
}

// -------- team partial-sum reduction through an idle smem ring slot ---------
template <int N>
__device__ __forceinline__ void team_reduce(u64* acc, float* redf, int team, int tidB)
{
    u64* red = (u64*)redf;
    if (team) {
        #pragma unroll
        for (int j = 0; j < N; j++) red[j * 256 + tidB] = acc[j];
    }
    __syncthreads();
    if (!team) {
        #pragma unroll
        for (int j = 0; j < N; j++) fadd2(acc[j], red[j * 256 + tidB]);
    }
    __syncthreads();
}

__global__ void __launch_bounds__(NTHR, 1)
recurrent_kernel(const float* __restrict__ inputs,
                 const float* __restrict__ Whp, const float* __restrict__ bhp,
                 const float* __restrict__ Wcp, const float* __restrict__ bcp,
                 const float* __restrict__ Wm,  const float* __restrict__ bm,
                 const float* __restrict__ Whpost, const float* __restrict__ bhpost,
                 const float* __restrict__ Wr1, const float* __restrict__ br1,
                 const float* __restrict__ Wr2, const float* __restrict__ br2,
                 float* __restrict__ out)
{
    extern __shared__ float smem[];
    float* Whp_p    = smem;                 // 8192  (256k packed)
    float* Wr1_p    = Whp_p    + 8192;      // 8192
    float* Wm_p     = Wr1_p    + 8192;      // 16384 (512k packed)
    float* Whpost_p = Wm_p     + 16384;     // 8192
    float* Wcp_p    = Whpost_p + 8192;      // 2048  (64k packed)
    float* bias_s   = Wcp_p    + 2048;      // 192
    float* bufs     = bias_s   + 192;       // 3 x 4096

    const int tid  = threadIdx.x;
    const int team = tid >> 8;         // 0 or 1 (k-split team)
    const int tidB = tid & 255;        // index within team
    const int wid8 = tidB >> 5;        // team-local warp 0..7
    const int lane = tid & 31;
    const int wr = wid8 & 1;           // row half (32 rows)
    const int wc = wid8 >> 1;          // col group 0..3 (8 cols each)
    const int lr = lane >> 2;          // lane row 0..7
    const int lc = lane & 3;           // lane col 0..3
    const int plbase = wr * 16 + lr * 2;   // first local pair (of 2)
    const int cc     = wc * 8 + lc * 2;    // first local col (of 2)
    const int aoff   = plbase * 2;
    const int cc2    = cc * 2;

    const int bi   = blockIdx.x >> 3;   // row tile 0..15
    const int bj   = blockIdx.x & 7;    // col tile 0..7
    const int row0 = bi * BM;
    const int c0   = bj * BN;

    const int hbase   = bi * (RDIM * BM);       // 16384 floats per tile
    const int catbase = bi * (2 * RDIM * BM);   // 32768

    // ---- build packed weight slices: Wp[(k>>1)*64 + col*2 + (k&1)] ----
    for (int i = tid; i < 256 * BN; i += NTHR) {
        int k = i >> 5, col = i & 31;
        int d = (k >> 1) * 64 + col * 2 + (k & 1);
        Whp_p[d]    = Whp[k * RDIM + c0 + col];
        Wr1_p[d]    = Wr1[k * RDIM + c0 + col];
        Whpost_p[d] = Whpost[k * RDIM + c0 + col];
    }
    for (int i = tid; i < 512 * BN; i += NTHR) {
        int k = i >> 5, col = i & 31;
        Wm_p[(k >> 1) * 64 + col * 2 + (k & 1)] = Wm[k * RDIM + c0 + col];
    }
    for (int i = tid; i < 64 * BN; i += NTHR) {
        int k = i >> 5, col = i & 31;
        Wcp_p[(k >> 1) * 64 + col * 2 + (k & 1)] = Wcp[k * RDIM + c0 + col];
    }
    if (tid < 32) {
        bias_s[tid]       = bhp[c0 + tid];
        bias_s[32 + tid]  = bcp[c0 + tid];
        bias_s[64 + tid]  = bm[c0 + tid];
        bias_s[96 + tid]  = bhpost[c0 + tid];
        bias_s[128 + tid] = br1[c0 + tid];
        bias_s[160 + tid] = Wr2[c0 + tid];
    }
    const float br2v = __ldg(br2);
    __syncthreads();

    for (int t = 0; t < T_STEPS; t++) {
        // ================= Phase A =================
        // ---- stage x_t (row-major, XOR-swizzled 16B slots) into buf0 ----
        {
            const float* xg = inputs + (size_t)t * NBATCH * IDIM + (size_t)row0 * IDIM;
            int u = tid;
            #pragma unroll
            for (int i = 0; i < 2; i++, u += NTHR) {
                int r = u >> 4, s = u & 15;
                cp_async16(bufs + r * 64 + ((s ^ ((r >> 2) & 7)) << 2),
                           xg + r * 64 + s * 4);
            }
            cp_commit();
            cp_wait<0>();
            __syncthreads();
        }
        // ---- S0: tcp = tanh(x @ Wcp + bcp), team-split over k ----
        {
            float aS[4];
            #pragma unroll
            for (int j = 0; j < 4; j++) aS[j] = team ? 0.f : bias_s[16 + cc - cc + 32 + cc] * 0.f + bias_s[32 + cc];
            // (team A carries bias; team B starts at 0)
            if (team) { aS[0] = aS[1] = aS[2] = aS[3] = 0.f; }
            else { aS[0] = aS[1] = bias_s[32 + cc]; aS[2] = aS[3] = bias_s[32 + cc + 1]; }
            // aS layout: [0]=row j0 c0, [1]=row j1 c0 ... use [rowj][col] flattened below
            float aT[4][2];
            #pragma unroll
            for (int j = 0; j < 4; j++) {
                aT[j][0] = team ? 0.f : bias_s[32 + cc];
                aT[j][1] = team ? 0.f : bias_s[32 + cc + 1];
            }
            #pragma unroll
            for (int k4i = 0; k4i < 8; k4i++) {
                int k4 = team * 8 + k4i;
                float4 wA = *(const float4*)(Wcp_p + (2 * k4) * 64 + cc2);
                float4 wB = *(const float4*)(Wcp_p + (2 * k4 + 1) * 64 + cc2);
                #pragma unroll
                for (int j = 0; j < 4; j++) {
                    int r = wr * 32 + lr * 4 + j;
                    float4 a = *(const float4*)(bufs + r * 64 + ((k4 ^ ((r >> 2) & 7)) << 2));
                    aT[j][0] = fmaf(a.x, wA.x, aT[j][0]);
                    aT[j][0] = fmaf(a.y, wA.y, aT[j][0]);
                    aT[j][0] = fmaf(a.z, wB.x, aT[j][0]);
                    aT[j][0] = fmaf(a.w, wB.y, aT[j][0]);
                    aT[j][1] = fmaf(a.x, wA.z, aT[j][1]);
                    aT[j][1] = fmaf(a.y, wA.w, aT[j][1]);
                    aT[j][1] = fmaf(a.z, wB.z, aT[j][1]);
                    aT[j][1] = fmaf(a.w, wB.w, aT[j][1]);
                }
            }
            // reduce team partials through buf1
            float* redf = bufs + 4096;
            if (team) {
                #pragma unroll
                for (int j = 0; j < 4; j++) {
                    redf[(2 * j) * 256 + tidB]     = aT[j][0];
                    redf[(2 * j + 1) * 256 + tidB] = aT[j][1];
                }
            }
            __syncthreads();
            if (!team) {
                #pragma unroll
                for (int j = 0; j < 4; j++) {
                    aT[j][0] += redf[(2 * j) * 256 + tidB];
                    aT[j][1] += redf[(2 * j + 1) * 256 + tidB];
                }
            }
            __syncthreads();
            if (!team) {
                #pragma unroll
                for (int ci = 0; ci < 2; ci++) {
                    size_t xcol = catbase + (size_t)(RDIM + c0 + cc + ci) * 64;
                    *(float2*)(g_cat + xcol + plbase * 2)
                        = make_float2(tanhf(aT[0][ci]), tanhf(aT[1][ci]));
                    *(float2*)(g_cat + xcol + (plbase + 1) * 2)
                        = make_float2(tanhf(aT[2][ci]), tanhf(aT[3][ci]));
                }
            }
        }

        if (t > 0) {
            // ---- S1 + S4 fused: a = tanh(h@Whp+bhp); r = h@Wr1+br1 ----
            u64 acc_a[4], acc_r[4];
            if (team) {
                acc_a[0] = acc_a[1] = acc_a[2] = acc_a[3] = 0;
                acc_r[0] = acc_r[1] = acc_r[2] = acc_r[3] = 0;
            } else {
                acc_a[0] = acc_a[1] = dup2(bias_s[cc]);
                acc_a[2] = acc_a[3] = dup2(bias_s[cc + 1]);
                acc_r[0] = acc_r[1] = dup2(bias_s[128 + cc]);
                acc_r[2] = acc_r[3] = dup2(bias_s[128 + cc + 1]);
            }
            gemm_pipe<4, true>(g_h + hbase, Whp_p, Wr1_p, bufs,
                               acc_a, acc_r, aoff, cc2, team);
            // reduce 8 accs through ring slot (4%3)=1
            {
                float* redf = bufs + 4096;
                u64* red = (u64*)redf;
                if (team) {
                    #pragma unroll
                    for (int j = 0; j < 4; j++) {
                        red[j * 256 + tidB]       = acc_a[j];
                        red[(4 + j) * 256 + tidB] = acc_r[j];
                    }
                }
                __syncthreads();
                if (!team) {
                    #pragma unroll
                    for (int j = 0; j < 4; j++) {
                        fadd2(acc_a[j], red[j * 256 + tidB]);
                        fadd2(acc_r[j], red[(4 + j) * 256 + tidB]);
                    }
                }
                __syncthreads();
            }
            if (!team) {
                #pragma unroll
                for (int ci = 0; ci < 2; ci++) {
                    size_t acol = catbase + (size_t)(c0 + cc + ci) * 64;
                    #pragma unroll
                    for (int p = 0; p < 2; p++) {
                        float2 f = unpack2(acc_a[ci * 2 + p]);
                        *(float2*)(g_cat + acol + (plbase + p) * 2)
                            = make_float2(tanhf(f.x), tanhf(f.y));
                    }
                }
                // S4 partial: v[row] = sum_cols relu(r)*Wr2[col]
                float w20 = bias_s[160 + cc], w21 = bias_s[160 + cc + 1];
                float2 r00 = unpack2(acc_r[0]), r10 = unpack2(acc_r[1]);
                float2 r01 = unpack2(acc_r[2]), r11 = unpack2(acc_r[3]);
                float v0 = fmaxf(r00.x, 0.f) * w20 + fmaxf(r01.x, 0.f) * w21;
                float v1 = fmaxf(r00.y, 0.f) * w20 + fmaxf(r01.y, 0.f) * w21;
                float v2 = fmaxf(r10.x, 0.f) * w20 + fmaxf(r11.x, 0.f) * w21;
                float v3 = fmaxf(r10.y, 0.f) * w20 + fmaxf(r11.y, 0.f) * w21;
                #pragma unroll
                for (int off = 1; off <= 2; off <<= 1) {
                    v0 += __shfl_xor_sync(0xffffffffu, v0, off);
                    v1 += __shfl_xor_sync(0xffffffffu, v1, off);
                    v2 += __shfl_xor_sync(0xffffffffu, v2, off);
                    v3 += __shfl_xor_sync(0xffffffffu, v3, off);
                }
                if (lc == 0)
                    *(float4*)(g_r1p + (size_t)(bj * 4 + wc) * NBATCH + row0 + wr * 32 + lr * 4)
                        = make_float4(v0, v1, v2, v3);
            }
        } else if (!team) {
            // h0 == 0 -> cat[:,0:256] = tanh(bhp)
            #pragma unroll
            for (int ci = 0; ci < 2; ci++) {
                float av = tanhf(bias_s[cc + ci]);
                size_t acol = catbase + (size_t)(c0 + cc + ci) * 64;
                *(float2*)(g_cat + acol + plbase * 2)       = make_float2(av, av);
                *(float2*)(g_cat + acol + (plbase + 1) * 2) = make_float2(av, av);
            }
        }
        grid_barrier();

        // ================= Phase B: m = tanh(cat @ Wm + bm) =================
        // finalize out[t-1] first so its L2 latency overlaps the GEMM
        if (bj == 0 && t > 0 && tid < BM) {
            int n = row0 + tid;
            float s = br2v;
            #pragma unroll 8
            for (int q = 0; q < 32; q++)
                s += __ldcg(&g_r1p[(size_t)q * NBATCH + n]);
            out[(size_t)(t - 1) * NBATCH + n] = s;
        }
        {
            u64 acc[4];
            if (team) { acc[0] = acc[1] = acc[2] = acc[3] = 0; }
            else {
                acc[0] = acc[1] = dup2(bias_s[64 + cc]);
                acc[2] = acc[3] = dup2(bias_s[64 + cc + 1]);
            }
            gemm_pipe<8, false>(g_cat + catbase, Wm_p, Wm_p, bufs,
                                acc, acc, aoff, cc2, team);
            team_reduce<4>(acc, bufs + 2 * 4096, team, tidB);   // slot (8%3)=2
            if (!team) {
                #pragma unroll
                for (int ci = 0; ci < 2; ci++) {
                    size_t mcol = hbase + (size_t)(c0 + cc + ci) * 64;
                    #pragma unroll
                    for (int p = 0; p < 2; p++) {
                        float2 f = unpack2(acc[ci * 2 + p]);
                        *(float2*)(g_m + mcol + (plbase + p) * 2)
                            = make_float2(tanhf(f.x), tanhf(f.y));
                    }
                }
            }
        }
        grid_barrier();

        // ================= Phase C: h = tanh(m @ Whpost + bhpost) ============
        {
            u64 acc[4];
            if (team) { acc[0] = acc[1] = acc[2] = acc[3] = 0; }
            else {
                acc[0] = acc[1] = dup2(bias_s[96 + cc]);
                acc[2] = acc[3] = dup2(bias_s[96 + cc + 1]);
            }
            gemm_pipe<4, false>(g_m + hbase, Whpost_p, Whpost_p, bufs,
                                acc, acc, aoff, cc2, team);
            team_reduce<4>(acc, bufs + 4096, team, tidB);       // slot (4%3)=1
            if (!team) {
                #pragma unroll
                for (int ci = 0; ci < 2; ci++) {
                    size_t hcol = hbase + (size_t)(c0 + cc + ci) * 64;
                    #pragma unroll
                    for (int p = 0; p < 2; p++) {
                        float2 f = unpack2(acc[ci * 2 + p]);
                        *(float2*)(g_h + hcol + (plbase + p) * 2)
                            = make_float2(tanhf(f.x), tanhf(f.y));
                    }
                }
            }
        }
        grid_barrier();
    }

    // ================= Epilogue: regressor for final step =================
    {
        u64 acc[4];
        if (team) { acc[0] = acc[1] = acc[2] = acc[3] = 0; }
        else {
            acc[0] = acc[1] = dup2(bias_s[128 + cc]);
            acc[2] = acc[3] = dup2(bias_s[128 + cc + 1]);
        }
        gemm_pipe<4, false>(g_h + hbase, Wr1_p, Wr1_p, bufs, acc, acc, aoff, cc2, team);
        team_reduce<4>(acc, bufs + 4096, team, tidB);
        if (!team) {
            float w20 = bias_s[160 + cc], w21 = bias_s[160 + cc + 1];
            float2 r00 = unpack2(acc[0]), r10 = unpack2(acc[1]);
            float2 r01 = unpack2(acc[2]), r11 = unpack2(acc[3]);
            float v0 = fmaxf(r00.x, 0.f) * w20 + fmaxf(r01.x, 0.f) * w21;
            float v1 = fmaxf(r00.y, 0.f) * w20 + fmaxf(r01.y, 0.f) * w21;
            float v2 = fmaxf(r10.x, 0.f) * w20 + fmaxf(r11.x, 0.f) * w21;
            float v3 = fmaxf(r10.y, 0.f) * w20 + fmaxf(r11.y, 0.f) * w21;
            #pragma unroll
            for (int off = 1; off <= 2; off <<= 1) {
                v0 += __shfl_xor_sync(0xffffffffu, v0, off);
                v1 += __shfl_xor_sync(0xffffffffu, v1, off);
                v2 += __shfl_xor_sync(0xffffffffu, v2, off);
                v3 += __shfl_xor_sync(0xffffffffu, v3, off);
            }
            if (lc == 0)
                *(float4*)(g_r1p + (size_t)(bj * 4 + wc) * NBATCH + row0 + wr * 32 + lr * 4)
                    = make_float4(v0, v1, v2, v3);
        }
    }
    grid_barrier();
    if (bj == 0 && tid < BM) {
        int n = row0 + tid;
        float s = br2v;
        #pragma unroll 8
        for (int q = 0; q < 32; q++)
            s += __ldcg(&g_r1p[(size_t)q * NBATCH + n]);
        out[(size_t)(T_STEPS - 1) * NBATCH + n] = s;
    }
}

extern "C" void kernel_launch(void* const* d_in, const int* in_sizes, int n_in,
                              void* d_out, int out_size)
{
    (void)in_sizes; (void)n_in; (void)out_size;
    const float* inputs = (const float*)d_in[0];
    const float* Whp    = (const float*)d_in[1];
    const float* bhp    = (const float*)d_in[2];
    const float* Wcp    = (const float*)d_in[3];
    const float* bcp    = (const float*)d_in[4];
    const float* Wm     = (const float*)d_in[5];
    const float* bm     = (const float*)d_in[6];
    const float* Whpost = (const float*)d_in[7];
    const float* bhpost = (const float*)d_in[8];
    const float* Wr1    = (const float*)d_in[9];
    const float* br1    = (const float*)d_in[10];
    const float* Wr2    = (const float*)d_in[11];
    const float* br2    = (const float*)d_in[12];
    float* out = (float*)d_out;

    // smem: packed weights 43008 + bias 192 + 3x4096 staging = 55488 floats
    //     = 221,952 B per CTA -> 1 CTA/SM
    const size_t smem_bytes = (size_t)55488 * sizeof(float);
    cudaFuncSetAttribute(recurrent_kernel,
                         cudaFuncAttributeMaxDynamicSharedMemorySize,
                         (int)smem_bytes);

    recurrent_kernel<<<NCTA, NTHR, smem_bytes>>>(
        inputs, Whp, bhp, Wcp, bcp, Wm, bm, Whpost, bhpost,
        Wr1, br1, Wr2, br2, out);
}